// round 6
// baseline (speedup 1.0000x reference)
#include <cuda_runtime.h>
#include <cuda_bf16.h>
#include <cstdint>

#define N_EMBED 384
#define NUM_EXPERTS 8
#define THREADS 256
#define TOK_PER_BLK 256             // 1 token per thread
#define KC 32                       // k-chunk staged in smem
#define PITCH 36                    // floats per token row (conflict-free .128 phases)
#define NCHUNK (N_EMBED / KC)       // 12

#define WS_BYTES (NUM_EXPERTS * N_EMBED * 8)          // 24576
#define XS_OFF   (WS_BYTES + 64)                      // 24640 (sb in the 64B gap)
#define XS_BUF_FLOATS (TOK_PER_BLK * PITCH)           // 9216 floats = 36864 B
#define SMEM_TOTAL (XS_OFF + 2 * XS_BUF_FLOATS * 4)   // 98368 B  -> 2 CTAs/SM

typedef unsigned long long ull;

__device__ __forceinline__ void ffma2(ull& a, ull b, ull c) {
    asm("fma.rn.f32x2 %0, %1, %2, %0;" : "+l"(a) : "l"(b), "l"(c));
}
__device__ __forceinline__ ull bcast2(float v) {
    ull r; asm("mov.b64 %0, {%1, %1};" : "=l"(r) : "f"(v)); return r;
}
__device__ __forceinline__ ull pack2(float lo, float hi) {
    ull r; asm("mov.b64 %0, {%1, %2};" : "=l"(r) : "f"(lo), "f"(hi)); return r;
}
__device__ __forceinline__ void unpack2(ull a, float& lo, float& hi) {
    asm("mov.b64 {%0, %1}, %2;" : "=f"(lo), "=f"(hi) : "l"(a));
}
__device__ __forceinline__ uint32_t smem_u32(const void* p) {
    return (uint32_t)__cvta_generic_to_shared(p);
}
__device__ __forceinline__ void cp16(uint32_t dst, const void* src, int pred) {
    asm volatile(
        "{ .reg .pred q; setp.ne.b32 q, %2, 0;\n\t"
        "@q cp.async.ca.shared.global [%0], [%1], 16; }"
        :: "r"(dst), "l"(src), "r"(pred));
}

__global__ __launch_bounds__(THREADS, 2)
void noisy_topk_router_kernel(
    const float* __restrict__ x,        // [n_tok, 384]
    const float* __restrict__ noise,    // [n_tok, 8]
    const float* __restrict__ w_route,  // [8, 384]
    const float* __restrict__ b_route,  // [8]
    const float* __restrict__ w_noise,  // [8, 384]
    const float* __restrict__ b_noise,  // [8]
    float* __restrict__ out,
    int n_tok, int write_idx)
{
    extern __shared__ char smem[];
    float2* ws = reinterpret_cast<float2*>(smem);                 // (route, noise) per [e][d]
    float*  sb = reinterpret_cast<float*>(smem + WS_BYTES);       // 16 biases
    float*  xs = reinterpret_cast<float*>(smem + XS_OFF);         // [2][256*36]

    const int tid = threadIdx.x;
    const int t0  = blockIdx.x * TOK_PER_BLK;
    const int t   = t0 + tid;

    // pack weights into smem
    for (int i = tid; i < NUM_EXPERTS * N_EMBED; i += THREADS)
        ws[i] = make_float2(w_route[i], w_noise[i]);
    if (tid < NUM_EXPERTS)           sb[tid] = b_route[tid];
    else if (tid < 2 * NUM_EXPERTS)  sb[tid] = b_noise[tid - NUM_EXPERTS];

    // ---- async staging of x chunks (8 float4 per thread per chunk) ----
    auto stage = [&](int c) {
        float* dst = xs + (c & 1) * XS_BUF_FLOATS;
#pragma unroll
        for (int r = 0; r < TOK_PER_BLK * (KC / 4) / THREADS; r++) {   // 8
            int idx = tid + r * THREADS;
            int tok = idx >> 3, q = idx & 7;
            const float* src = x + (size_t)(t0 + tok) * N_EMBED + c * KC + q * 4;
            cp16(smem_u32(dst + tok * PITCH + q * 4), src, (t0 + tok < n_tok) ? 1 : 0);
        }
        asm volatile("cp.async.commit_group;" ::: "memory");
    };

    stage(0);
    stage(1);
    asm volatile("cp.async.wait_group 1;" ::: "memory");   // chunk 0 landed (this thread)
    __syncthreads();                                       // xs c0 + ws + sb visible

    ull acc[NUM_EXPERTS];
#pragma unroll
    for (int e = 0; e < NUM_EXPERTS; e++)
        acc[e] = pack2(sb[e], sb[NUM_EXPERTS + e]);   // fold biases in

    for (int c = 0; c < NCHUNK; c++) {
        const float* buf = xs + (c & 1) * XS_BUF_FLOATS;
        const float* wp = reinterpret_cast<const float*>(smem) + c * KC * 2;  // [e][d] pairs, row e stride 768
#pragma unroll
        for (int j = 0; j < KC; j += 4) {
            float4 xv = *reinterpret_cast<const float4*>(&buf[tid * PITCH + j]);
            ull x0 = bcast2(xv.x), x1 = bcast2(xv.y);
            ull x2 = bcast2(xv.z), x3 = bcast2(xv.w);
#pragma unroll
            for (int e = 0; e < NUM_EXPERTS; e++) {
                ulonglong2 wa = *reinterpret_cast<const ulonglong2*>(wp + e * (N_EMBED * 2) + j * 2);
                ulonglong2 wb = *reinterpret_cast<const ulonglong2*>(wp + e * (N_EMBED * 2) + j * 2 + 4);
                ffma2(acc[e], x0, wa.x);
                ffma2(acc[e], x1, wa.y);
                ffma2(acc[e], x2, wb.x);
                ffma2(acc[e], x3, wb.y);
            }
        }
        __syncthreads();   // everyone done reading buf (c&1)
        if (c + 2 < NCHUNK) stage(c + 2);
        else asm volatile("cp.async.commit_group;" ::: "memory");   // keep group count moving
        asm volatile("cp.async.wait_group 1;" ::: "memory");        // chunk c+1 landed
        __syncthreads();
    }

    if (t >= n_tok) return;

    // ---- epilogue (thread == token; fully coalesced noise/out accesses) ----
    const float4* np = reinterpret_cast<const float4*>(noise + (size_t)t * NUM_EXPERTS);
    float4 nz0 = np[0], nz1 = np[1];
    float nz[NUM_EXPERTS] = {nz0.x, nz0.y, nz0.z, nz0.w, nz1.x, nz1.y, nz1.z, nz1.w};

    float v[NUM_EXPERTS];
#pragma unroll
    for (int e = 0; e < NUM_EXPERTS; e++) {
        float lg, nl;
        unpack2(acc[e], lg, nl);
        // jax.nn.softplus: max(x,0) + log1p(exp(-|x|))
        float sp = fmaxf(nl, 0.0f) + log1pf(expf(-fabsf(nl)));
        v[e] = lg + nz[e] * sp;
    }

    // top-2, first-occurrence tie-break (matches jax.lax.top_k)
    float v0 = v[0]; int i0 = 0;
#pragma unroll
    for (int e = 1; e < NUM_EXPERTS; e++)
        if (v[e] > v0) { v0 = v[e]; i0 = e; }
    float v1 = -3.402823466e+38f; int i1 = 0;
#pragma unroll
    for (int e = 0; e < NUM_EXPERTS; e++) {
        bool take = (e != i0) && (v[e] > v1);
        if (take) { v1 = v[e]; i1 = e; }
    }

    float e1 = expf(v1 - v0);
    float inv = 1.0f / (1.0f + e1);
    float p0 = inv, p1 = e1 * inv;

    float o[NUM_EXPERTS];
#pragma unroll
    for (int e = 0; e < NUM_EXPERTS; e++)
        o[e] = (e == i0) ? p0 : ((e == i1) ? p1 : 0.0f);

    float4* op = reinterpret_cast<float4*>(out + (size_t)t * NUM_EXPERTS);
    op[0] = make_float4(o[0], o[1], o[2], o[3]);
    op[1] = make_float4(o[4], o[5], o[6], o[7]);

    if (write_idx) {
        float2* ip = reinterpret_cast<float2*>(out + (size_t)n_tok * NUM_EXPERTS);
        ip[t] = make_float2((float)i0, (float)i1);
    }
}

extern "C" void kernel_launch(void* const* d_in, const int* in_sizes, int n_in,
                              void* d_out, int out_size) {
    const float* x       = (const float*)d_in[0];
    const float* noise   = (const float*)d_in[1];
    const float* w_route = (const float*)d_in[2];
    const float* b_route = (const float*)d_in[3];
    const float* w_noise = (const float*)d_in[4];
    const float* b_noise = (const float*)d_in[5];
    float* out = (float*)d_out;

    int n_tok = in_sizes[0] / N_EMBED;
    int write_idx = (out_size >= n_tok * NUM_EXPERTS + n_tok * 2) ? 1 : 0;

    cudaFuncSetAttribute(noisy_topk_router_kernel,
                         cudaFuncAttributeMaxDynamicSharedMemorySize, SMEM_TOTAL);

    int grid = (n_tok + TOK_PER_BLK - 1) / TOK_PER_BLK;
    noisy_topk_router_kernel<<<grid, THREADS, SMEM_TOTAL>>>(
        x, noise, w_route, b_route, w_noise, b_noise, out, n_tok, write_idx);
}

// round 7
// speedup vs baseline: 1.4581x; 1.4581x over previous
#include <cuda_runtime.h>
#include <cuda_bf16.h>
#include <cstdint>

#define N_EMBED 384
#define NUM_EXPERTS 8
#define THREADS 128
#define TOK_PER_BLK 128             // 64 token-slots x 2 tokens/thread; experts split 2-way
#define KC 16                       // k-chunk staged in smem
#define PITCH 20                    // floats/token row: 80B -> stride mod 128 = 16, conflict-free .128
#define NCHUNK (N_EMBED / KC)       // 24

#define WS_BYTES (NUM_EXPERTS * N_EMBED * 8)          // 24576
#define XS_OFF   (WS_BYTES + 64)                      // 24640 (sb in the gap)
#define XS_BUF_FLOATS (TOK_PER_BLK * PITCH)           // 2560 floats = 10240 B
#define SMEM_TOTAL (XS_OFF + 2 * XS_BUF_FLOATS * 4)   // 45120 B -> 5 CTAs/SM

typedef unsigned long long ull;

__device__ __forceinline__ void ffma2(ull& a, ull b, ull c) {
    asm("fma.rn.f32x2 %0, %1, %2, %0;" : "+l"(a) : "l"(b), "l"(c));
}
__device__ __forceinline__ ull bcast2(float v) {
    ull r; asm("mov.b64 %0, {%1, %1};" : "=l"(r) : "f"(v)); return r;
}
__device__ __forceinline__ ull pack2(float lo, float hi) {
    ull r; asm("mov.b64 %0, {%1, %2};" : "=l"(r) : "f"(lo), "f"(hi)); return r;
}
__device__ __forceinline__ void unpack2(ull a, float& lo, float& hi) {
    asm("mov.b64 {%0, %1}, %2;" : "=f"(lo), "=f"(hi) : "l"(a));
}
__device__ __forceinline__ uint32_t smem_u32(const void* p) {
    return (uint32_t)__cvta_generic_to_shared(p);
}
__device__ __forceinline__ void cp16(uint32_t dst, const void* src, int pred) {
    asm volatile(
        "{ .reg .pred q; setp.ne.b32 q, %2, 0;\n\t"
        "@q cp.async.ca.shared.global [%0], [%1], 16; }"
        :: "r"(dst), "l"(src), "r"(pred));
}

__global__ __launch_bounds__(THREADS, 5)
void noisy_topk_router_kernel(
    const float* __restrict__ x,        // [n_tok, 384]
    const float* __restrict__ noise,    // [n_tok, 8]
    const float* __restrict__ w_route,  // [8, 384]
    const float* __restrict__ b_route,  // [8]
    const float* __restrict__ w_noise,  // [8, 384]
    const float* __restrict__ b_noise,  // [8]
    float* __restrict__ out,
    int n_tok, int write_idx)
{
    extern __shared__ char smem[];
    float2* ws = reinterpret_cast<float2*>(smem);            // (route, noise) per [e][d]
    float*  sb = reinterpret_cast<float*>(smem + WS_BYTES);  // 16 biases
    float*  xs = reinterpret_cast<float*>(smem + XS_OFF);    // [2][128*20]

    const int tid  = threadIdx.x;
    const int half = tid >> 6;           // expert half: experts [half*4, half*4+4)
    const int tl   = tid & 63;           // token slot
    const int t0   = blockIdx.x * TOK_PER_BLK;
    const int tA   = t0 + tl;            // first token
    const int tB   = t0 + tl + 64;       // second token
    const int eb   = half * 4;           // expert base

    // pack weights into smem
    for (int i = tid; i < NUM_EXPERTS * N_EMBED; i += THREADS)
        ws[i] = make_float2(w_route[i], w_noise[i]);
    if (tid < NUM_EXPERTS)           sb[tid] = b_route[tid];
    else if (tid < 2 * NUM_EXPERTS)  sb[tid] = b_noise[tid - NUM_EXPERTS];

    // ---- async staging of x chunks (4 float4 per thread per chunk) ----
    auto stage = [&](int c) {
        float* dst = xs + (c & 1) * XS_BUF_FLOATS;
#pragma unroll
        for (int r = 0; r < TOK_PER_BLK * (KC / 4) / THREADS; r++) {   // 4
            int idx = tid + r * THREADS;
            int tok = idx >> 2, q = idx & 3;                           // 4 float4 per token-chunk
            const float* src = x + (size_t)(t0 + tok) * N_EMBED + c * KC + q * 4;
            cp16(smem_u32(dst + tok * PITCH + q * 4), src, (t0 + tok < n_tok) ? 1 : 0);
        }
        asm volatile("cp.async.commit_group;" ::: "memory");
    };

    stage(0);
    stage(1);
    asm volatile("cp.async.wait_group 1;" ::: "memory");
    __syncthreads();

    ull acc[2][4];
#pragma unroll
    for (int k = 0; k < 2; k++)
#pragma unroll
        for (int e = 0; e < 4; e++)
            acc[k][e] = pack2(sb[eb + e], sb[NUM_EXPERTS + eb + e]);   // fold biases

    const float* wsf = reinterpret_cast<const float*>(ws);

    for (int c = 0; c < NCHUNK; c++) {
        const float* buf = xs + (c & 1) * XS_BUF_FLOATS;
#pragma unroll
        for (int j = 0; j < KC; j += 4) {
            float4 va = *reinterpret_cast<const float4*>(&buf[tl * PITCH + j]);
            float4 vb = *reinterpret_cast<const float4*>(&buf[(tl + 64) * PITCH + j]);
            ull a0 = bcast2(va.x), a1 = bcast2(va.y), a2 = bcast2(va.z), a3 = bcast2(va.w);
            ull b0 = bcast2(vb.x), b1 = bcast2(vb.y), b2 = bcast2(vb.z), b3 = bcast2(vb.w);
            const int d = c * KC + j;
#pragma unroll
            for (int e = 0; e < 4; e++) {
                const float* wpe = wsf + ((eb + e) * N_EMBED + d) * 2;
                ulonglong2 wa = *reinterpret_cast<const ulonglong2*>(wpe);      // d, d+1
                ulonglong2 wb = *reinterpret_cast<const ulonglong2*>(wpe + 4);  // d+2, d+3
                ffma2(acc[0][e], a0, wa.x);
                ffma2(acc[1][e], b0, wa.x);
                ffma2(acc[0][e], a1, wa.y);
                ffma2(acc[1][e], b1, wa.y);
                ffma2(acc[0][e], a2, wb.x);
                ffma2(acc[1][e], b2, wb.x);
                ffma2(acc[0][e], a3, wb.y);
                ffma2(acc[1][e], b3, wb.y);
            }
        }
        __syncthreads();   // all readers of buf (c&1) done
        if (c + 2 < NCHUNK) stage(c + 2);
        else asm volatile("cp.async.commit_group;" ::: "memory");
        asm volatile("cp.async.wait_group 1;" ::: "memory");        // chunk c+1 landed
        __syncthreads();
    }

    // ---- per-(token, expert-half) noisy logits ----
    float v[2][4];
#pragma unroll
    for (int k = 0; k < 2; k++) {
        int t = (k == 0) ? tA : tB;
        float4 nz = make_float4(0.f, 0.f, 0.f, 0.f);
        if (t < n_tok)
            nz = *reinterpret_cast<const float4*>(noise + (size_t)t * NUM_EXPERTS + eb);
        float nza[4] = {nz.x, nz.y, nz.z, nz.w};
#pragma unroll
        for (int e = 0; e < 4; e++) {
            float lg, nl;
            unpack2(acc[k][e], lg, nl);
            // jax.nn.softplus: max(x,0) + log1p(exp(-|x|))
            float sp = fmaxf(nl, 0.0f) + log1pf(expf(-fabsf(nl)));
            v[k][e] = lg + nza[e] * sp;
        }
    }

    // exchange halves through smem (xs region is free now; barrier above guarantees)
    float* vsm = xs;                         // [128 tokens][8 experts] = 4KB
#pragma unroll
    for (int k = 0; k < 2; k++)
#pragma unroll
        for (int e = 0; e < 4; e++)
            vsm[(tl + k * 64) * 8 + eb + e] = v[k][e];
    __syncthreads();

    // ---- finalize: thread == token ----
    int t = t0 + tid;
    if (t >= n_tok) return;

    float va[NUM_EXPERTS];
#pragma unroll
    for (int e = 0; e < NUM_EXPERTS; e++) va[e] = vsm[tid * 8 + e];

    // top-2, first-occurrence tie-break (matches jax.lax.top_k)
    float v0 = va[0]; int i0 = 0;
#pragma unroll
    for (int e = 1; e < NUM_EXPERTS; e++)
        if (va[e] > v0) { v0 = va[e]; i0 = e; }
    float v1 = -3.402823466e+38f; int i1 = 0;
#pragma unroll
    for (int e = 0; e < NUM_EXPERTS; e++) {
        bool take = (e != i0) && (va[e] > v1);
        if (take) { v1 = va[e]; i1 = e; }
    }

    float e1 = expf(v1 - v0);
    float inv = 1.0f / (1.0f + e1);
    float p0 = inv, p1 = e1 * inv;

    float o[NUM_EXPERTS];
#pragma unroll
    for (int e = 0; e < NUM_EXPERTS; e++)
        o[e] = (e == i0) ? p0 : ((e == i1) ? p1 : 0.0f);

    float4* op = reinterpret_cast<float4*>(out + (size_t)t * NUM_EXPERTS);
    op[0] = make_float4(o[0], o[1], o[2], o[3]);
    op[1] = make_float4(o[4], o[5], o[6], o[7]);

    if (write_idx) {
        float2* ip = reinterpret_cast<float2*>(out + (size_t)n_tok * NUM_EXPERTS);
        ip[t] = make_float2((float)i0, (float)i1);
    }
}

extern "C" void kernel_launch(void* const* d_in, const int* in_sizes, int n_in,
                              void* d_out, int out_size) {
    const float* x       = (const float*)d_in[0];
    const float* noise   = (const float*)d_in[1];
    const float* w_route = (const float*)d_in[2];
    const float* b_route = (const float*)d_in[3];
    const float* w_noise = (const float*)d_in[4];
    const float* b_noise = (const float*)d_in[5];
    float* out = (float*)d_out;

    int n_tok = in_sizes[0] / N_EMBED;
    int write_idx = (out_size >= n_tok * NUM_EXPERTS + n_tok * 2) ? 1 : 0;

    cudaFuncSetAttribute(noisy_topk_router_kernel,
                         cudaFuncAttributeMaxDynamicSharedMemorySize, SMEM_TOTAL);

    int grid = (n_tok + TOK_PER_BLK - 1) / TOK_PER_BLK;   // 512
    noisy_topk_router_kernel<<<grid, THREADS, SMEM_TOTAL>>>(
        x, noise, w_route, b_route, w_noise, b_noise, out, n_tok, write_idx);
}

// round 8
// speedup vs baseline: 1.7475x; 1.1985x over previous
#include <cuda_runtime.h>
#include <cuda_bf16.h>
#include <cstdint>

#define N_EMBED 384
#define NUM_EXPERTS 8
#define THREADS 128
#define TOK_PER_BLK 256       // 64 token-slots x 4 tokens/thread; K split 2-way across thread halves
#define KC 32                 // 16 dims per K-half per chunk
#define KH 16                 // dims per half per chunk
#define PITCH 36              // floats per token row (conflict-free .128 phases)
#define NCHUNK 12             // 12 * 16 = 192 dims per half

#define WS_BYTES (NUM_EXPERTS * N_EMBED * 8)          // 24576
#define XS_OFF   (WS_BYTES + 64)                      // 24640 (sb in gap)
#define XS_BUF_FLOATS (TOK_PER_BLK * PITCH)           // 9216 floats = 36864 B
#define SMEM_TOTAL (XS_OFF + 2 * XS_BUF_FLOATS * 4)   // 98368 B -> 2 CTAs/SM

typedef unsigned long long ull;

__device__ __forceinline__ void ffma2(ull& a, ull b, ull c) {
    asm("fma.rn.f32x2 %0, %1, %2, %0;" : "+l"(a) : "l"(b), "l"(c));
}
__device__ __forceinline__ ull bcast2(float v) {
    ull r; asm("mov.b64 %0, {%1, %1};" : "=l"(r) : "f"(v)); return r;
}
__device__ __forceinline__ ull pack2(float lo, float hi) {
    ull r; asm("mov.b64 %0, {%1, %2};" : "=l"(r) : "f"(lo), "f"(hi)); return r;
}
__device__ __forceinline__ void unpack2(ull a, float& lo, float& hi) {
    asm("mov.b64 {%0, %1}, %2;" : "=f"(lo), "=f"(hi) : "l"(a));
}
__device__ __forceinline__ uint32_t smem_u32(const void* p) {
    return (uint32_t)__cvta_generic_to_shared(p);
}
__device__ __forceinline__ void cp16(uint32_t dst, const void* src, int pred) {
    asm volatile(
        "{ .reg .pred q; setp.ne.b32 q, %2, 0;\n\t"
        "@q cp.async.ca.shared.global [%0], [%1], 16; }"
        :: "r"(dst), "l"(src), "r"(pred));
}

__global__ __launch_bounds__(THREADS, 2)
void noisy_topk_router_kernel(
    const float* __restrict__ x,        // [n_tok, 384]
    const float* __restrict__ noise,    // [n_tok, 8]
    const float* __restrict__ w_route,  // [8, 384]
    const float* __restrict__ b_route,  // [8]
    const float* __restrict__ w_noise,  // [8, 384]
    const float* __restrict__ b_noise,  // [8]
    float* __restrict__ out,
    int n_tok, int write_idx)
{
    extern __shared__ char smem[];
    float2* ws = reinterpret_cast<float2*>(smem);            // (route, noise) per [e][d]
    float*  sb = reinterpret_cast<float*>(smem + WS_BYTES);  // 16 biases
    float*  xs = reinterpret_cast<float*>(smem + XS_OFF);    // [2][256*36]

    const int tid  = threadIdx.x;
    const int half = tid >> 6;            // K-half: dims [half*192, half*192+192)
    const int tl   = tid & 63;            // token slot base; tokens tl, tl+64, tl+128, tl+192
    const int t0   = blockIdx.x * TOK_PER_BLK;
    const int D0   = half * 192;

    // pack weights into smem
    for (int i = tid; i < NUM_EXPERTS * N_EMBED; i += THREADS)
        ws[i] = make_float2(w_route[i], w_noise[i]);
    if (tid < NUM_EXPERTS)           sb[tid] = b_route[tid];
    else if (tid < 2 * NUM_EXPERTS)  sb[tid] = b_noise[tid - NUM_EXPERTS];

    // ---- staging: chunk c = 16 dims from EACH half, per token (32 floats) ----
    // row layout: floats [0..15] = dims [c*16, c*16+16), floats [16..31] = dims [192+c*16, ...)
    auto stage = [&](int c) {
        float* dst = xs + (c & 1) * XS_BUF_FLOATS;
#pragma unroll
        for (int r = 0; r < 16; r++) {                 // 2048 float4 / 128 threads
            int idx = tid + r * THREADS;
            int tok = idx >> 3, q = idx & 7;
            int dim = c * KH + q * 4 + ((q >> 2) * (192 - KH));   // q<4: half0, q>=4: half1
            const float* src = x + (size_t)(t0 + tok) * N_EMBED + dim;
            cp16(smem_u32(dst + tok * PITCH + q * 4), src, (t0 + tok < n_tok) ? 1 : 0);
        }
        asm volatile("cp.async.commit_group;" ::: "memory");
    };

    stage(0);
    stage(1);
    asm volatile("cp.async.wait_group 1;" ::: "memory");
    __syncthreads();

    ull acc[4][NUM_EXPERTS];
#pragma unroll
    for (int k = 0; k < 4; k++)
#pragma unroll
        for (int e = 0; e < NUM_EXPERTS; e++)
            acc[k][e] = (half == 0 && k < 4) ? pack2(sb[e], sb[NUM_EXPERTS + e]) : 0ull;
    if (half == 1) {
#pragma unroll
        for (int k = 0; k < 4; k++)
#pragma unroll
            for (int e = 0; e < NUM_EXPERTS; e++)
                acc[k][e] = 0ull;
    }

    const float* wsf = reinterpret_cast<const float*>(ws);

    for (int c = 0; c < NCHUNK; c++) {
        const float* buf = xs + (c & 1) * XS_BUF_FLOATS + half * KH;
#pragma unroll
        for (int j = 0; j < KH; j += 4) {
            ull xb[4][4];
#pragma unroll
            for (int k = 0; k < 4; k++) {
                float4 xv = *reinterpret_cast<const float4*>(&buf[(tl + k * 64) * PITCH + j]);
                xb[k][0] = bcast2(xv.x); xb[k][1] = bcast2(xv.y);
                xb[k][2] = bcast2(xv.z); xb[k][3] = bcast2(xv.w);
            }
            const int d = D0 + c * KH + j;
#pragma unroll
            for (int e = 0; e < NUM_EXPERTS; e++) {
                const float* wpe = wsf + (e * N_EMBED + d) * 2;
                ulonglong2 wa = *reinterpret_cast<const ulonglong2*>(wpe);      // dims d, d+1
                ulonglong2 wb = *reinterpret_cast<const ulonglong2*>(wpe + 4);  // dims d+2, d+3
#pragma unroll
                for (int k = 0; k < 4; k++) {
                    ffma2(acc[k][e], xb[k][0], wa.x);
                    ffma2(acc[k][e], xb[k][1], wa.y);
                    ffma2(acc[k][e], xb[k][2], wb.x);
                    ffma2(acc[k][e], xb[k][3], wb.y);
                }
            }
        }
        __syncthreads();   // readers of buf (c&1) done
        if (c + 2 < NCHUNK) stage(c + 2);
        else asm volatile("cp.async.commit_group;" ::: "memory");
        asm volatile("cp.async.wait_group 1;" ::: "memory");
        __syncthreads();
    }

    // ---- exchange partial sums through smem (xs is free now) ----
    // vsm[half][tok][e] : float2 pairs, 2*256*8*8B = 32 KB
    float2* vsm = reinterpret_cast<float2*>(xs);
#pragma unroll
    for (int k = 0; k < 4; k++) {
        int tok = tl + k * 64;
#pragma unroll
        for (int e = 0; e < NUM_EXPERTS; e++) {
            float lo, hi; unpack2(acc[k][e], lo, hi);
            vsm[((half * TOK_PER_BLK + tok) * NUM_EXPERTS) + e] = make_float2(lo, hi);
        }
    }
    __syncthreads();

    // ---- finalize: 128 threads x 2 tokens (tid, tid+128) ----
#pragma unroll
    for (int k = 0; k < 2; k++) {
        int tok = tid + k * THREADS;
        int t = t0 + tok;
        if (t >= n_tok) continue;

        const float4* np = reinterpret_cast<const float4*>(noise + (size_t)t * NUM_EXPERTS);
        float4 nz0 = np[0], nz1 = np[1];
        float nz[NUM_EXPERTS] = {nz0.x, nz0.y, nz0.z, nz0.w, nz1.x, nz1.y, nz1.z, nz1.w};

        float v[NUM_EXPERTS];
#pragma unroll
        for (int e = 0; e < NUM_EXPERTS; e++) {
            float2 p0h = vsm[(tok * NUM_EXPERTS) + e];
            float2 p1h = vsm[((TOK_PER_BLK + tok) * NUM_EXPERTS) + e];
            float lg = p0h.x + p1h.x;
            float nl = p0h.y + p1h.y;
            // jax.nn.softplus: max(x,0) + log1p(exp(-|x|))
            float sp = fmaxf(nl, 0.0f) + log1pf(expf(-fabsf(nl)));
            v[e] = lg + nz[e] * sp;
        }

        // top-2, first-occurrence tie-break (matches jax.lax.top_k)
        float v0 = v[0]; int i0 = 0;
#pragma unroll
        for (int e = 1; e < NUM_EXPERTS; e++)
            if (v[e] > v0) { v0 = v[e]; i0 = e; }
        float v1 = -3.402823466e+38f; int i1 = 0;
#pragma unroll
        for (int e = 0; e < NUM_EXPERTS; e++) {
            bool take = (e != i0) && (v[e] > v1);
            if (take) { v1 = v[e]; i1 = e; }
        }

        float e1 = expf(v1 - v0);
        float inv = 1.0f / (1.0f + e1);
        float p0 = inv, p1 = e1 * inv;

        float o[NUM_EXPERTS];
#pragma unroll
        for (int e = 0; e < NUM_EXPERTS; e++)
            o[e] = (e == i0) ? p0 : ((e == i1) ? p1 : 0.0f);

        float4* op = reinterpret_cast<float4*>(out + (size_t)t * NUM_EXPERTS);
        op[0] = make_float4(o[0], o[1], o[2], o[3]);
        op[1] = make_float4(o[4], o[5], o[6], o[7]);

        if (write_idx) {
            float2* ip = reinterpret_cast<float2*>(out + (size_t)n_tok * NUM_EXPERTS);
            ip[t] = make_float2((float)i0, (float)i1);
        }
    }
}

extern "C" void kernel_launch(void* const* d_in, const int* in_sizes, int n_in,
                              void* d_out, int out_size) {
    const float* x       = (const float*)d_in[0];
    const float* noise   = (const float*)d_in[1];
    const float* w_route = (const float*)d_in[2];
    const float* b_route = (const float*)d_in[3];
    const float* w_noise = (const float*)d_in[4];
    const float* b_noise = (const float*)d_in[5];
    float* out = (float*)d_out;

    int n_tok = in_sizes[0] / N_EMBED;
    int write_idx = (out_size >= n_tok * NUM_EXPERTS + n_tok * 2) ? 1 : 0;

    cudaFuncSetAttribute(noisy_topk_router_kernel,
                         cudaFuncAttributeMaxDynamicSharedMemorySize, SMEM_TOTAL);

    int grid = (n_tok + TOK_PER_BLK - 1) / TOK_PER_BLK;   // 256
    noisy_topk_router_kernel<<<grid, THREADS, SMEM_TOTAL>>>(
        x, noise, w_route, b_route, w_noise, b_noise, out, n_tok, write_idx);
}